// round 14
// baseline (speedup 1.0000x reference)
#include <cuda_runtime.h>
#include <math.h>

#define NNODES 50000
#define NEDGES 800000

// ---------------- f32x2 packed-math helpers (sm_103a FFMA2) ----------------
__device__ __forceinline__ unsigned long long pk2(float lo, float hi) {
    unsigned long long r;
    asm("mov.b64 %0, {%1, %2};" : "=l"(r) : "f"(lo), "f"(hi));
    return r;
}
__device__ __forceinline__ unsigned long long spl2(float x) {
    unsigned long long r;
    asm("mov.b64 %0, {%1, %1};" : "=l"(r) : "f"(x));
    return r;
}
__device__ __forceinline__ void upk2(unsigned long long v, float& lo, float& hi) {
    asm("mov.b64 {%0, %1}, %2;" : "=f"(lo), "=f"(hi) : "l"(v));
}
__device__ __forceinline__ unsigned long long ffma2_(unsigned long long a,
                                                    unsigned long long b,
                                                    unsigned long long c) {
    unsigned long long d;
    asm("fma.rn.f32x2 %0, %1, %2, %3;" : "=l"(d) : "l"(a), "l"(b), "l"(c));
    return d;
}
__device__ __forceinline__ unsigned long long fmul2_(unsigned long long a,
                                                     unsigned long long b) {
    unsigned long long d;
    asm("mul.rn.f32x2 %0, %1, %2;" : "=l"(d) : "l"(a), "l"(b));
    return d;
}

// ---------------- scratch (static __device__ — no allocations) ----------------
__device__ __align__(16) float g_xl[NNODES * 128];
__device__ __align__(16) float g_xr[NNODES * 128];
__device__ __align__(16) float g_res[NNODES * 128];
__device__ __align__(16) float g_h1[NNODES * 32];
__device__ __align__(16) float g_h2[NNODES * 128];
__device__ __align__(16) float g_loop[NNODES * 8];
__device__ __align__(16) float g_eaP[NEDGES * 8];    // edge_attr permuted to CSR order
__device__ int g_deg[NNODES];
__device__ int g_rowptr[NNODES + 1];
__device__ int g_wptr[NNODES];
__device__ int g_bsum[1024];
__device__ int g_colsrc[NEDGES];

// ---------------- CSR build ----------------
__global__ void hist_kernel(const int* __restrict__ dst, int* __restrict__ deg, int e) {
    int i = blockIdx.x * blockDim.x + threadIdx.x;
    if (i < e) atomicAdd(&deg[dst[i]], 1);
}

__global__ void blocksum_kernel(const int* __restrict__ deg, int* __restrict__ bsum, int n) {
    __shared__ int sh[32];
    int tid = threadIdx.x, lane = tid & 31, wid = tid >> 5;
    int i = blockIdx.x * 1024 + tid;
    int v = (i < n) ? deg[i] : 0;
    #pragma unroll
    for (int off = 16; off > 0; off >>= 1) v += __shfl_xor_sync(0xffffffffu, v, off);
    if (lane == 0) sh[wid] = v;
    __syncthreads();
    if (wid == 0) {
        int x = sh[lane];
        #pragma unroll
        for (int off = 16; off > 0; off >>= 1) x += __shfl_xor_sync(0xffffffffu, x, off);
        if (lane == 0) bsum[blockIdx.x] = x;
    }
}

__global__ void scanpart_kernel(int* __restrict__ b, int g) {
    __shared__ int ws[32];
    int tid = threadIdx.x, lane = tid & 31, wid = tid >> 5;
    int v = (tid < g) ? b[tid] : 0;
    int x = v;
    #pragma unroll
    for (int off = 1; off < 32; off <<= 1) {
        int t = __shfl_up_sync(0xffffffffu, x, off);
        if (lane >= off) x += t;
    }
    if (lane == 31) ws[wid] = x;
    __syncthreads();
    if (wid == 0) {
        int y = ws[lane];
        #pragma unroll
        for (int off = 1; off < 32; off <<= 1) {
            int t = __shfl_up_sync(0xffffffffu, y, off);
            if (lane >= off) y += t;
        }
        ws[lane] = y;
    }
    __syncthreads();
    int excl = x - v + (wid > 0 ? ws[wid - 1] : 0);
    if (tid < g) b[tid] = excl;
}

__global__ void scanfinal_kernel(const int* __restrict__ deg, const int* __restrict__ bsum,
                                 int* __restrict__ rowptr, int* __restrict__ wptr,
                                 int n, int e) {
    __shared__ int ws[32];
    int tid = threadIdx.x, lane = tid & 31, wid = tid >> 5;
    int i = blockIdx.x * 1024 + tid;
    int v = (i < n) ? deg[i] : 0;
    int x = v;
    #pragma unroll
    for (int off = 1; off < 32; off <<= 1) {
        int t = __shfl_up_sync(0xffffffffu, x, off);
        if (lane >= off) x += t;
    }
    if (lane == 31) ws[wid] = x;
    __syncthreads();
    if (wid == 0) {
        int y = ws[lane];
        #pragma unroll
        for (int off = 1; off < 32; off <<= 1) {
            int t = __shfl_up_sync(0xffffffffu, y, off);
            if (lane >= off) y += t;
        }
        ws[lane] = y;
    }
    __syncthreads();
    int excl = x - v + (wid > 0 ? ws[wid - 1] : 0) + bsum[blockIdx.x];
    if (i < n) { rowptr[i] = excl; wptr[i] = excl; }
    if (blockIdx.x == 0 && tid == 0) rowptr[n] = e;
}

// scatter src ids AND permute edge_attr into CSR order (eaP)
__global__ void scatter_kernel(const int* __restrict__ src, const int* __restrict__ dst,
                               const float* __restrict__ eattr, int* __restrict__ wptr,
                               int* __restrict__ colsrc, float* __restrict__ eaP, int e) {
    int i = blockIdx.x * blockDim.x + threadIdx.x;
    if (i >= e) return;
    int d = dst[i];
    int p = atomicAdd(&wptr[d], 1);
    colsrc[p] = src[i];
    float4 a = *(const float4*)(eattr + (size_t)i * 8);
    float4 b = *(const float4*)(eattr + (size_t)i * 8 + 4);
    *(float4*)(eaP + (size_t)p * 8) = a;
    *(float4*)(eaP + (size_t)p * 8 + 4) = b;
}

// loop-attr mean from CSR (coalesced sequential reads of eaP), divide folded in
__global__ void loopattr_kernel(const int* __restrict__ rowptr, const float* __restrict__ eaP,
                                float* __restrict__ loopv, int n) {
    int tid = blockIdx.x * blockDim.x + threadIdx.x;
    int g = tid >> 3, c = tid & 7;
    if (g >= n) return;
    int rs = rowptr[g], re = rowptr[g + 1];
    float s = 0.f;
    for (int k = rs; k < re; k++) s += eaP[(size_t)k * 8 + c];
    int d = re - rs;
    loopv[g * 8 + c] = s / (float)(d > 0 ? d : 1);
}

// ---------------- dense GEMM: up to NW weight sets sharing A (f32x2 inner) ----------------
template <int K, int DOUT, int NW, int ROWS, int KC>
__global__ void gemm_multi(const float* __restrict__ A,
                           const float* __restrict__ W0, const float* __restrict__ b0, float* __restrict__ O0,
                           const float* __restrict__ W1, const float* __restrict__ b1, float* __restrict__ O1,
                           const float* __restrict__ W2, const float* __restrict__ b2, float* __restrict__ O2,
                           int n) {
    constexpr int COLS = DOUT * NW;
    constexpr int TX = COLS / 4;
    constexpr int TY = ROWS / 4;
    constexpr int NT = TX * TY;
    constexpr bool STAGE = (K * COLS * 4 <= 40960);
    constexpr int SWSZ = STAGE ? K * COLS : 4;
    __shared__ __align__(16) float sW[SWSZ];
    __shared__ float sA[KC][ROWS + 1];
    int tid = threadIdx.x;
    if (STAGE) {
        for (int idx = tid; idx < K * DOUT; idx += NT) {
            int k = idx / DOUT, c = idx % DOUT;
            sW[k * COLS + c] = W0[idx];
            if (NW > 1) sW[k * COLS + DOUT + c] = W1[idx];
            if (NW > 2) sW[k * COLS + 2 * DOUT + c] = W2[idx];
        }
    }
    int tx = tid % TX, ty = tid / TX;
    int cg = tx * 4;
    int which = cg / DOUT, col = cg % DOUT;
    const float* bb = (which == 0) ? b0 : (which == 1) ? b1 : b2;
    const float* Wp = (which == 0) ? W0 : (which == 1) ? W1 : W2;
    int row0 = blockIdx.x * ROWS;

    // packed accumulators: a01 = (c,c+1), a23 = (c+2,c+3)
    unsigned long long a01[4], a23[4];
    {
        unsigned long long i01 = pk2(bb[col + 0], bb[col + 1]);
        unsigned long long i23 = pk2(bb[col + 2], bb[col + 3]);
        #pragma unroll
        for (int i = 0; i < 4; i++) { a01[i] = i01; a23[i] = i23; }
    }

    for (int kc0 = 0; kc0 < K; kc0 += KC) {
        __syncthreads();
        for (int idx = tid; idx < ROWS * KC; idx += NT) {
            int r = idx / KC, k = idx % KC;
            int gr = row0 + r;
            sA[k][r] = (gr < n) ? A[(size_t)gr * K + kc0 + k] : 0.f;
        }
        __syncthreads();
        #pragma unroll
        for (int k = 0; k < KC; k++) {
            unsigned long long rb01, rb23;
            if (STAGE) {
                ulonglong2 rbp = *(const ulonglong2*)&sW[(kc0 + k) * COLS + cg];
                rb01 = rbp.x; rb23 = rbp.y;
            } else {
                ulonglong2 rbp = *(const ulonglong2*)&Wp[(size_t)(kc0 + k) * DOUT + col];
                rb01 = rbp.x; rb23 = rbp.y;
            }
            #pragma unroll
            for (int i = 0; i < 4; i++) {
                unsigned long long ras = spl2(sA[k][ty * 4 + i]);
                a01[i] = ffma2_(ras, rb01, a01[i]);
                a23[i] = ffma2_(ras, rb23, a23[i]);
            }
        }
    }
    float* O = (which == 0) ? O0 : (which == 1) ? O1 : O2;
    #pragma unroll
    for (int i = 0; i < 4; i++) {
        int gr = row0 + ty * 4 + i;
        if (gr < n) {
            float v0, v1, v2, v3;
            upk2(a01[i], v0, v1);
            upk2(a23[i], v2, v3);
            *(float4*)&O[(size_t)gr * DOUT + col] = make_float4(v0, v1, v2, v3);
        }
    }
}

// ---------------- fused GATv2 edge pass, VEC=1 layers (f32x2-packed dot) ----------------
//   layer1: GROUP=8   (D=32, H=4)
//   layer3: GROUP=32  (D=32, H=1)
// Per-edge dot We·ea packed: ev pairs come free from ulonglong2 loads of eaP;
// rWe pre-packed as 4 q-pair registers. 8 FMA -> 1 FMUL2 + 3 FFMA2 + add.
template <int GROUP, bool RELU>
__global__ __launch_bounds__(256) void agg_kernel(
    const float* __restrict__ xl, const float* __restrict__ xr,
    const float* __restrict__ eaP, const float* __restrict__ We,
    const float* __restrict__ att, const float* __restrict__ bias,
    const int* __restrict__ rowptr, const int* __restrict__ colsrc,
    const float* __restrict__ loopattr, float* __restrict__ out, int n) {
    constexpr int D = 32;
    int tid = threadIdx.x, lane = tid & 31, wid = tid >> 5;
    int dst = blockIdx.x * 8 + wid;
    if (dst >= n) return;

    const int ch0 = lane;

    // rWe packed as q-pairs: rWeq[p] = (We[2p][ch], We[2p+1][ch])
    unsigned long long rWeq[4];
    #pragma unroll
    for (int p = 0; p < 4; p++)
        rWeq[p] = pk2(__ldg(We + (2 * p) * D + ch0), __ldg(We + (2 * p + 1) * D + ch0));

    float attv = __ldg(att + ch0);
    float xrv = xr[(size_t)dst * D + ch0];
    float num = 0.f, den = 0.f;

    auto ldE = [&](unsigned long long* d, const float* p) {
        ulonglong2 a = *(const ulonglong2*)p;
        ulonglong2 b = *(const ulonglong2*)(p + 4);
        d[0] = a.x; d[1] = a.y; d[2] = b.x; d[3] = b.y;
    };
    auto body = [&](float xv, const unsigned long long* ep) {
        unsigned long long acc = fmul2_(ep[3], rWeq[3]);
        acc = ffma2_(ep[2], rWeq[2], acc);
        acc = ffma2_(ep[1], rWeq[1], acc);
        acc = ffma2_(ep[0], rWeq[0], acc);
        float lo, hi;
        upk2(acc, lo, hi);
        float t = lo + hi + xv + xrv;
        float s = fmaxf(t, 0.f) + 0.2f * fminf(t, 0.f);
        float p = s * attv;
        #pragma unroll
        for (int off = GROUP / 2; off > 0; off >>= 1)
            p += __shfl_xor_sync(0xffffffffu, p, off);
        float w = __expf(p);
        num = fmaf(w, xv, num);
        den += w;
    };

    int rs = rowptr[dst], re = rowptr[dst + 1];

    float px0, px1;
    unsigned long long pe0[4], pe1[4];
    if (rs < re) {
        int s = colsrc[rs];
        ldE(pe0, eaP + (size_t)rs * 8);
        px0 = xl[(size_t)s * D + ch0];
    }
    if (rs + 1 < re) {
        int s = colsrc[rs + 1];
        ldE(pe1, eaP + (size_t)(rs + 1) * 8);
        px1 = xl[(size_t)s * D + ch0];
    }
    {   // self loop
        unsigned long long se[4];
        float sx = xl[(size_t)dst * D + ch0];
        ldE(se, loopattr + (size_t)dst * 8);
        body(sx, se);
    }
    int k = rs;
    while (k < re) {
        {
            float cx = px0;
            unsigned long long ce[4];
            #pragma unroll
            for (int q = 0; q < 4; q++) ce[q] = pe0[q];
            if (k + 2 < re) {
                int s = colsrc[k + 2];
                ldE(pe0, eaP + (size_t)(k + 2) * 8);
                px0 = xl[(size_t)s * D + ch0];
            }
            body(cx, ce);
        }
        k++;
        if (k >= re) break;
        {
            float cx = px1;
            unsigned long long ce[4];
            #pragma unroll
            for (int q = 0; q < 4; q++) ce[q] = pe1[q];
            if (k + 2 < re) {
                int s = colsrc[k + 2];
                ldE(pe1, eaP + (size_t)(k + 2) * 8);
                px1 = xl[(size_t)s * D + ch0];
            }
            body(cx, ce);
        }
        k++;
    }

    float val = num / den;
    if (bias) val += bias[ch0];
    if (RELU) val = fmaxf(val, 0.f);
    out[(size_t)dst * D + ch0] = val;
}

// ---------------- layer-2 edge pass: D=128, H=4, q-packed f32x2 body ----------------
// lane owns channels lane*4..lane*4+3 (all in head lane>>3 -> GROUP=8 reduce).
// Depth-3 rotating software pipeline.
__global__ __launch_bounds__(256) void agg2_kernel(
    const float* __restrict__ xl, const float* __restrict__ xr,
    const float* __restrict__ eaP, const float* __restrict__ We,
    const float* __restrict__ att, const float* __restrict__ pre,
    const int* __restrict__ rowptr, const int* __restrict__ colsrc,
    const float* __restrict__ loopattr, float* __restrict__ out, int n) {
    constexpr int D = 128;
    int tid = threadIdx.x, lane = tid & 31, wid = tid >> 5;
    int dst = blockIdx.x * 8 + wid;
    if (dst >= n) return;

    const int ch0 = lane * 4;

    unsigned long long weq[4][4];
    #pragma unroll
    for (int p = 0; p < 4; p++)
        #pragma unroll
        for (int v = 0; v < 4; v++)
            weq[p][v] = pk2(__ldg(We + (2 * p) * D + ch0 + v),
                            __ldg(We + (2 * p + 1) * D + ch0 + v));

    float attv[4], xrv[4], num[4];
    float den = 0.f;
    {
        float4 a = __ldg((const float4*)(att + ch0));
        attv[0] = a.x; attv[1] = a.y; attv[2] = a.z; attv[3] = a.w;
        float4 r = *(const float4*)(xr + (size_t)dst * D + ch0);
        xrv[0] = r.x; xrv[1] = r.y; xrv[2] = r.z; xrv[3] = r.w;
    }
    #pragma unroll
    for (int v = 0; v < 4; v++) num[v] = 0.f;

    auto ldX = [&](float* d, const float* p) {
        float4 t = *(const float4*)p;
        d[0] = t.x; d[1] = t.y; d[2] = t.z; d[3] = t.w;
    };
    auto ldE = [&](unsigned long long* d, const float* p) {
        ulonglong2 a = *(const ulonglong2*)p;
        ulonglong2 b = *(const ulonglong2*)(p + 4);
        d[0] = a.x; d[1] = a.y; d[2] = b.x; d[3] = b.y;
    };
    auto body = [&](const float* xv, const unsigned long long* ep) {
        float pp = 0.f;
        #pragma unroll
        for (int v = 0; v < 4; v++) {
            unsigned long long acc = fmul2_(ep[3], weq[3][v]);
            acc = ffma2_(ep[2], weq[2][v], acc);
            acc = ffma2_(ep[1], weq[1][v], acc);
            acc = ffma2_(ep[0], weq[0][v], acc);
            float lo, hi;
            upk2(acc, lo, hi);
            float t = lo + hi + xv[v] + xrv[v];
            float s = fmaxf(t, 0.f) + 0.2f * fminf(t, 0.f);
            pp = fmaf(s, attv[v], pp);
        }
        pp += __shfl_xor_sync(0xffffffffu, pp, 4);
        pp += __shfl_xor_sync(0xffffffffu, pp, 2);
        pp += __shfl_xor_sync(0xffffffffu, pp, 1);
        float w = __expf(pp);
        #pragma unroll
        for (int v = 0; v < 4; v++) num[v] = fmaf(w, xv[v], num[v]);
        den += w;
    };

    int rs = rowptr[dst], re = rowptr[dst + 1];

    // depth-3 rotating pipeline, compile-time slots
    float px0[4], px1[4], px2[4];
    unsigned long long pe0[4], pe1[4], pe2[4];
#define PREF2(X, EA, IDX) do { int kk = (IDX); if (kk < re) { \
        int s_ = colsrc[kk]; \
        ldE(EA, eaP + (size_t)kk * 8); \
        ldX(X, xl + (size_t)s_ * D + ch0); } } while (0)
    PREF2(px0, pe0, rs);
    PREF2(px1, pe1, rs + 1);
    PREF2(px2, pe2, rs + 2);
    {   // self loop (its loads overlap the prefetches above)
        float sx[4];
        unsigned long long se[4];
        ldX(sx, xl + (size_t)dst * D + ch0);
        ldE(se, loopattr + (size_t)dst * 8);
        body(sx, se);
    }
    int k = rs;
    while (k < re) {
        {
            float cx[4];
            unsigned long long ce[4];
            #pragma unroll
            for (int v = 0; v < 4; v++) cx[v] = px0[v];
            #pragma unroll
            for (int q = 0; q < 4; q++) ce[q] = pe0[q];
            PREF2(px0, pe0, k + 3);
            body(cx, ce);
        }
        if (++k >= re) break;
        {
            float cx[4];
            unsigned long long ce[4];
            #pragma unroll
            for (int v = 0; v < 4; v++) cx[v] = px1[v];
            #pragma unroll
            for (int q = 0; q < 4; q++) ce[q] = pe1[q];
            PREF2(px1, pe1, k + 3);
            body(cx, ce);
        }
        if (++k >= re) break;
        {
            float cx[4];
            unsigned long long ce[4];
            #pragma unroll
            for (int v = 0; v < 4; v++) cx[v] = px2[v];
            #pragma unroll
            for (int q = 0; q < 4; q++) ce[q] = pe2[q];
            PREF2(px2, pe2, k + 3);
            body(cx, ce);
        }
        ++k;
    }
#undef PREF2

    float res[4];
    #pragma unroll
    for (int v = 0; v < 4; v++) {
        float val = num[v] / den;
        val += pre[(size_t)dst * D + ch0 + v];
        res[v] = fmaxf(val, 0.f);
    }
    *(float4*)&out[(size_t)dst * D + ch0] = make_float4(res[0], res[1], res[2], res[3]);
}

// ---------------- host launcher ----------------
extern "C" void kernel_launch(void* const* d_in, const int* in_sizes, int n_in,
                              void* d_out, int out_size) {
    const float* x     = (const float*)d_in[0];
    const int*   eidx  = (const int*)d_in[1];
    const float* eattr = (const float*)d_in[2];
    const float* Wl1 = (const float*)d_in[3];
    const float* bl1 = (const float*)d_in[4];
    const float* Wr1 = (const float*)d_in[5];
    const float* br1 = (const float*)d_in[6];
    const float* We1 = (const float*)d_in[7];
    const float* att1 = (const float*)d_in[8];
    const float* b1 = (const float*)d_in[9];
    const float* Wl2 = (const float*)d_in[10];
    const float* bl2 = (const float*)d_in[11];
    const float* Wr2 = (const float*)d_in[12];
    const float* br2 = (const float*)d_in[13];
    const float* We2 = (const float*)d_in[14];
    const float* att2 = (const float*)d_in[15];
    const float* b2 = (const float*)d_in[16];
    const float* Rw2 = (const float*)d_in[17];
    const float* Wl3 = (const float*)d_in[18];
    const float* bl3 = (const float*)d_in[19];
    const float* Wr3 = (const float*)d_in[20];
    const float* br3 = (const float*)d_in[21];
    const float* We3 = (const float*)d_in[22];
    const float* att3 = (const float*)d_in[23];
    const float* b3 = (const float*)d_in[24];

    int Nn = in_sizes[0] / 16;   // 50000
    int Ee = in_sizes[1] / 2;    // 800000
    const int* srcp = eidx;
    const int* dstp = eidx + Ee;

    float *xl, *xr, *res, *h1, *h2, *loopw, *eaP;
    int *deg, *rowptr, *wptr, *bsum, *colsrc;
    cudaGetSymbolAddress((void**)&xl, g_xl);
    cudaGetSymbolAddress((void**)&xr, g_xr);
    cudaGetSymbolAddress((void**)&res, g_res);
    cudaGetSymbolAddress((void**)&h1, g_h1);
    cudaGetSymbolAddress((void**)&h2, g_h2);
    cudaGetSymbolAddress((void**)&loopw, g_loop);
    cudaGetSymbolAddress((void**)&eaP, g_eaP);
    cudaGetSymbolAddress((void**)&deg, g_deg);
    cudaGetSymbolAddress((void**)&rowptr, g_rowptr);
    cudaGetSymbolAddress((void**)&wptr, g_wptr);
    cudaGetSymbolAddress((void**)&bsum, g_bsum);
    cudaGetSymbolAddress((void**)&colsrc, g_colsrc);

    int G = (Nn + 1023) / 1024;  // 49

    // ---- CSR + permuted eattr + self-loop attr ----
    cudaMemsetAsync(deg, 0, Nn * sizeof(int));
    hist_kernel<<<(Ee + 255) / 256, 256>>>(dstp, deg, Ee);
    blocksum_kernel<<<G, 1024>>>(deg, bsum, Nn);
    scanpart_kernel<<<1, 1024>>>(bsum, G);
    scanfinal_kernel<<<G, 1024>>>(deg, bsum, rowptr, wptr, Nn, Ee);
    scatter_kernel<<<(Ee + 255) / 256, 256>>>(srcp, dstp, eattr, wptr, colsrc, eaP, Ee);
    loopattr_kernel<<<(Nn * 8 + 255) / 256, 256>>>(rowptr, eaP, loopw, Nn);

    // ---- layer 1: in=16 -> D=32 (H=4), relu ----
    gemm_multi<16, 32, 2, 32, 16><<<(Nn + 31) / 32, 128>>>(
        x, Wl1, bl1, xl, Wr1, br1, xr, nullptr, nullptr, nullptr, Nn);
    agg_kernel<8, true><<<(Nn + 7) / 8, 256>>>(
        xl, xr, eaP, We1, att1, b1, rowptr, colsrc, loopw, h1, Nn);

    // ---- layer 2: in=32 -> D=128 (H=4), residual h1@Rw2 + b2, relu (3 GEMMs fused) ----
    gemm_multi<32, 128, 3, 16, 32><<<(Nn + 15) / 16, 384>>>(
        h1, Wl2, bl2, xl, Wr2, br2, xr, Rw2, b2, res, Nn);
    agg2_kernel<<<(Nn + 7) / 8, 256>>>(
        xl, xr, eaP, We2, att2, res, rowptr, colsrc, loopw, h2, Nn);

    // ---- layer 3: in=128 -> D=32 (H=1), no relu ----
    gemm_multi<128, 32, 2, 32, 32><<<(Nn + 31) / 32, 128>>>(
        h2, Wl3, bl3, xl, Wr3, br3, xr, nullptr, nullptr, nullptr, Nn);
    agg_kernel<32, false><<<(Nn + 7) / 8, 256>>>(
        xl, xr, eaP, We3, att3, b3, rowptr, colsrc, loopw, (float*)d_out, Nn);
}

// round 15
// speedup vs baseline: 1.0558x; 1.0558x over previous
#include <cuda_runtime.h>
#include <math.h>

#define NNODES 50000
#define NEDGES 800000

// ---------------- f32x2 packed-math helpers (sm_103a FFMA2) ----------------
__device__ __forceinline__ unsigned long long pk2(float lo, float hi) {
    unsigned long long r;
    asm("mov.b64 %0, {%1, %2};" : "=l"(r) : "f"(lo), "f"(hi));
    return r;
}
__device__ __forceinline__ unsigned long long spl2(float x) {
    unsigned long long r;
    asm("mov.b64 %0, {%1, %1};" : "=l"(r) : "f"(x));
    return r;
}
__device__ __forceinline__ void upk2(unsigned long long v, float& lo, float& hi) {
    asm("mov.b64 {%0, %1}, %2;" : "=f"(lo), "=f"(hi) : "l"(v));
}
__device__ __forceinline__ unsigned long long ffma2_(unsigned long long a,
                                                    unsigned long long b,
                                                    unsigned long long c) {
    unsigned long long d;
    asm("fma.rn.f32x2 %0, %1, %2, %3;" : "=l"(d) : "l"(a), "l"(b), "l"(c));
    return d;
}
__device__ __forceinline__ unsigned long long fmul2_(unsigned long long a,
                                                     unsigned long long b) {
    unsigned long long d;
    asm("mul.rn.f32x2 %0, %1, %2;" : "=l"(d) : "l"(a), "l"(b));
    return d;
}

// ---------------- scratch (static __device__ — no allocations) ----------------
__device__ __align__(16) float g_xl[NNODES * 128];
__device__ __align__(16) float g_xr[NNODES * 128];
__device__ __align__(16) float g_res[NNODES * 128];
__device__ __align__(16) float g_h1[NNODES * 32];
__device__ __align__(16) float g_h2[NNODES * 128];
__device__ __align__(16) float g_loop[NNODES * 8];
__device__ __align__(16) float g_eaP[NEDGES * 8];    // edge_attr permuted to CSR order
__device__ int g_deg[NNODES];                        // zero-invariant across replays
__device__ int g_rowptr[NNODES + 1];
__device__ int g_wptr[NNODES];
__device__ int g_bsum[1024];
__device__ int g_colsrc[NEDGES];

// ---------------- CSR build ----------------
__global__ void hist_kernel(const int* __restrict__ dst, int* __restrict__ deg, int e) {
    int i = blockIdx.x * blockDim.x + threadIdx.x;
    if (i < e) atomicAdd(&deg[dst[i]], 1);
}

__global__ void blocksum_kernel(const int* __restrict__ deg, int* __restrict__ bsum, int n) {
    __shared__ int sh[32];
    int tid = threadIdx.x, lane = tid & 31, wid = tid >> 5;
    int i = blockIdx.x * 1024 + tid;
    int v = (i < n) ? deg[i] : 0;
    #pragma unroll
    for (int off = 16; off > 0; off >>= 1) v += __shfl_xor_sync(0xffffffffu, v, off);
    if (lane == 0) sh[wid] = v;
    __syncthreads();
    if (wid == 0) {
        int x = sh[lane];
        #pragma unroll
        for (int off = 16; off > 0; off >>= 1) x += __shfl_xor_sync(0xffffffffu, x, off);
        if (lane == 0) bsum[blockIdx.x] = x;
    }
}

__global__ void scanpart_kernel(int* __restrict__ b, int g) {
    __shared__ int ws[32];
    int tid = threadIdx.x, lane = tid & 31, wid = tid >> 5;
    int v = (tid < g) ? b[tid] : 0;
    int x = v;
    #pragma unroll
    for (int off = 1; off < 32; off <<= 1) {
        int t = __shfl_up_sync(0xffffffffu, x, off);
        if (lane >= off) x += t;
    }
    if (lane == 31) ws[wid] = x;
    __syncthreads();
    if (wid == 0) {
        int y = ws[lane];
        #pragma unroll
        for (int off = 1; off < 32; off <<= 1) {
            int t = __shfl_up_sync(0xffffffffu, y, off);
            if (lane >= off) y += t;
        }
        ws[lane] = y;
    }
    __syncthreads();
    int excl = x - v + (wid > 0 ? ws[wid - 1] : 0);
    if (tid < g) b[tid] = excl;
}

// final scan: writes rowptr & wptr, AND re-zeroes deg (last reader; restores
// the zero-invariant so the next graph replay's hist starts from zero).
__global__ void scanfinal_kernel(int* __restrict__ deg, const int* __restrict__ bsum,
                                 int* __restrict__ rowptr, int* __restrict__ wptr,
                                 int n, int e) {
    __shared__ int ws[32];
    int tid = threadIdx.x, lane = tid & 31, wid = tid >> 5;
    int i = blockIdx.x * 1024 + tid;
    int v = (i < n) ? deg[i] : 0;
    if (i < n) deg[i] = 0;
    int x = v;
    #pragma unroll
    for (int off = 1; off < 32; off <<= 1) {
        int t = __shfl_up_sync(0xffffffffu, x, off);
        if (lane >= off) x += t;
    }
    if (lane == 31) ws[wid] = x;
    __syncthreads();
    if (wid == 0) {
        int y = ws[lane];
        #pragma unroll
        for (int off = 1; off < 32; off <<= 1) {
            int t = __shfl_up_sync(0xffffffffu, y, off);
            if (lane >= off) y += t;
        }
        ws[lane] = y;
    }
    __syncthreads();
    int excl = x - v + (wid > 0 ? ws[wid - 1] : 0) + bsum[blockIdx.x];
    if (i < n) { rowptr[i] = excl; wptr[i] = excl; }
    if (blockIdx.x == 0 && tid == 0) rowptr[n] = e;
}

// scatter src ids AND permute edge_attr into CSR order (eaP)
__global__ void scatter_kernel(const int* __restrict__ src, const int* __restrict__ dst,
                               const float* __restrict__ eattr, int* __restrict__ wptr,
                               int* __restrict__ colsrc, float* __restrict__ eaP, int e) {
    int i = blockIdx.x * blockDim.x + threadIdx.x;
    if (i >= e) return;
    int d = dst[i];
    int p = atomicAdd(&wptr[d], 1);
    colsrc[p] = src[i];
    float4 a = *(const float4*)(eattr + (size_t)i * 8);
    float4 b = *(const float4*)(eattr + (size_t)i * 8 + 4);
    *(float4*)(eaP + (size_t)p * 8) = a;
    *(float4*)(eaP + (size_t)p * 8 + 4) = b;
}

// loop-attr mean from CSR (coalesced sequential reads of eaP), divide folded in
__global__ void loopattr_kernel(const int* __restrict__ rowptr, const float* __restrict__ eaP,
                                float* __restrict__ loopv, int n) {
    int tid = blockIdx.x * blockDim.x + threadIdx.x;
    int g = tid >> 3, c = tid & 7;
    if (g >= n) return;
    int rs = rowptr[g], re = rowptr[g + 1];
    float s = 0.f;
    for (int k = rs; k < re; k++) s += eaP[(size_t)k * 8 + c];
    int d = re - rs;
    loopv[g * 8 + c] = s / (float)(d > 0 ? d : 1);
}

// ---------------- dense GEMM: up to NW weight sets sharing A (f32x2 inner) ----------------
template <int K, int DOUT, int NW, int ROWS, int KC>
__global__ void gemm_multi(const float* __restrict__ A,
                           const float* __restrict__ W0, const float* __restrict__ b0, float* __restrict__ O0,
                           const float* __restrict__ W1, const float* __restrict__ b1, float* __restrict__ O1,
                           const float* __restrict__ W2, const float* __restrict__ b2, float* __restrict__ O2,
                           int n) {
    constexpr int COLS = DOUT * NW;
    constexpr int TX = COLS / 4;
    constexpr int TY = ROWS / 4;
    constexpr int NT = TX * TY;
    constexpr bool STAGE = (K * COLS * 4 <= 40960);
    constexpr int SWSZ = STAGE ? K * COLS : 4;
    __shared__ __align__(16) float sW[SWSZ];
    __shared__ float sA[KC][ROWS + 1];
    int tid = threadIdx.x;
    if (STAGE) {
        for (int idx = tid; idx < K * DOUT; idx += NT) {
            int k = idx / DOUT, c = idx % DOUT;
            sW[k * COLS + c] = W0[idx];
            if (NW > 1) sW[k * COLS + DOUT + c] = W1[idx];
            if (NW > 2) sW[k * COLS + 2 * DOUT + c] = W2[idx];
        }
    }
    int tx = tid % TX, ty = tid / TX;
    int cg = tx * 4;
    int which = cg / DOUT, col = cg % DOUT;
    const float* bb = (which == 0) ? b0 : (which == 1) ? b1 : b2;
    const float* Wp = (which == 0) ? W0 : (which == 1) ? W1 : W2;
    int row0 = blockIdx.x * ROWS;

    // packed accumulators: a01 = (c,c+1), a23 = (c+2,c+3)
    unsigned long long a01[4], a23[4];
    {
        unsigned long long i01 = pk2(bb[col + 0], bb[col + 1]);
        unsigned long long i23 = pk2(bb[col + 2], bb[col + 3]);
        #pragma unroll
        for (int i = 0; i < 4; i++) { a01[i] = i01; a23[i] = i23; }
    }

    for (int kc0 = 0; kc0 < K; kc0 += KC) {
        __syncthreads();
        for (int idx = tid; idx < ROWS * KC; idx += NT) {
            int r = idx / KC, k = idx % KC;
            int gr = row0 + r;
            sA[k][r] = (gr < n) ? A[(size_t)gr * K + kc0 + k] : 0.f;
        }
        __syncthreads();
        #pragma unroll
        for (int k = 0; k < KC; k++) {
            unsigned long long rb01, rb23;
            if (STAGE) {
                ulonglong2 rbp = *(const ulonglong2*)&sW[(kc0 + k) * COLS + cg];
                rb01 = rbp.x; rb23 = rbp.y;
            } else {
                ulonglong2 rbp = *(const ulonglong2*)&Wp[(size_t)(kc0 + k) * DOUT + col];
                rb01 = rbp.x; rb23 = rbp.y;
            }
            #pragma unroll
            for (int i = 0; i < 4; i++) {
                unsigned long long ras = spl2(sA[k][ty * 4 + i]);
                a01[i] = ffma2_(ras, rb01, a01[i]);
                a23[i] = ffma2_(ras, rb23, a23[i]);
            }
        }
    }
    float* O = (which == 0) ? O0 : (which == 1) ? O1 : O2;
    #pragma unroll
    for (int i = 0; i < 4; i++) {
        int gr = row0 + ty * 4 + i;
        if (gr < n) {
            float v0, v1, v2, v3;
            upk2(a01[i], v0, v1);
            upk2(a23[i], v2, v3);
            *(float4*)&O[(size_t)gr * DOUT + col] = make_float4(v0, v1, v2, v3);
        }
    }
}

// ---------------- fused GATv2 edge pass, VEC=1 layers (R13 scalar form) ----------------
//   layer1: GROUP=8   (D=32, H=4)
//   layer3: GROUP=32  (D=32, H=1)
template <int GROUP, bool RELU>
__global__ __launch_bounds__(256) void agg_kernel(
    const float* __restrict__ xl, const float* __restrict__ xr,
    const float* __restrict__ eaP, const float* __restrict__ We,
    const float* __restrict__ att, const float* __restrict__ bias,
    const int* __restrict__ rowptr, const int* __restrict__ colsrc,
    const float* __restrict__ loopattr, float* __restrict__ out, int n) {
    constexpr int D = 32;
    int tid = threadIdx.x, lane = tid & 31, wid = tid >> 5;
    int dst = blockIdx.x * 8 + wid;
    if (dst >= n) return;

    const int ch0 = lane;

    float rWe[8];
    #pragma unroll
    for (int q = 0; q < 8; q++) rWe[q] = __ldg(We + q * D + ch0);

    float attv = __ldg(att + ch0);
    float xrv = xr[(size_t)dst * D + ch0];
    float num = 0.f, den = 0.f;

    auto ldE = [&](float* d, const float* p) {
        float4 a = *(const float4*)p;
        float4 b = *(const float4*)(p + 4);
        d[0] = a.x; d[1] = a.y; d[2] = a.z; d[3] = a.w;
        d[4] = b.x; d[5] = b.y; d[6] = b.z; d[7] = b.w;
    };
    auto body = [&](float xv, const float* ev) {
        float m = 0.f;
        #pragma unroll
        for (int q = 0; q < 8; q++) m = fmaf(ev[q], rWe[q], m);
        float t = m + xv + xrv;
        float s = fmaxf(t, 0.f) + 0.2f * fminf(t, 0.f);
        float p = s * attv;
        #pragma unroll
        for (int off = GROUP / 2; off > 0; off >>= 1)
            p += __shfl_xor_sync(0xffffffffu, p, off);
        float w = __expf(p);
        num = fmaf(w, xv, num);
        den += w;
    };

    int rs = rowptr[dst], re = rowptr[dst + 1];

    float px0, pe0[8], px1, pe1[8];
    if (rs < re) {
        int s = colsrc[rs];
        ldE(pe0, eaP + (size_t)rs * 8);
        px0 = xl[(size_t)s * D + ch0];
    }
    if (rs + 1 < re) {
        int s = colsrc[rs + 1];
        ldE(pe1, eaP + (size_t)(rs + 1) * 8);
        px1 = xl[(size_t)s * D + ch0];
    }
    {   // self loop
        float se[8];
        float sx = xl[(size_t)dst * D + ch0];
        ldE(se, loopattr + (size_t)dst * 8);
        body(sx, se);
    }
    int k = rs;
    while (k < re) {
        {
            float cx = px0, ce[8];
            #pragma unroll
            for (int q = 0; q < 8; q++) ce[q] = pe0[q];
            if (k + 2 < re) {
                int s = colsrc[k + 2];
                ldE(pe0, eaP + (size_t)(k + 2) * 8);
                px0 = xl[(size_t)s * D + ch0];
            }
            body(cx, ce);
        }
        k++;
        if (k >= re) break;
        {
            float cx = px1, ce[8];
            #pragma unroll
            for (int q = 0; q < 8; q++) ce[q] = pe1[q];
            if (k + 2 < re) {
                int s = colsrc[k + 2];
                ldE(pe1, eaP + (size_t)(k + 2) * 8);
                px1 = xl[(size_t)s * D + ch0];
            }
            body(cx, ce);
        }
        k++;
    }

    float val = num / den;
    if (bias) val += bias[ch0];
    if (RELU) val = fmaxf(val, 0.f);
    out[(size_t)dst * D + ch0] = val;
}

// ---------------- layer-2 edge pass: D=128, H=4, q-packed f32x2 body ----------------
// lane owns channels lane*4..lane*4+3 (all in head lane>>3 -> GROUP=8 reduce).
// Depth-3 rotating software pipeline.
__global__ __launch_bounds__(256) void agg2_kernel(
    const float* __restrict__ xl, const float* __restrict__ xr,
    const float* __restrict__ eaP, const float* __restrict__ We,
    const float* __restrict__ att, const float* __restrict__ pre,
    const int* __restrict__ rowptr, const int* __restrict__ colsrc,
    const float* __restrict__ loopattr, float* __restrict__ out, int n) {
    constexpr int D = 128;
    int tid = threadIdx.x, lane = tid & 31, wid = tid >> 5;
    int dst = blockIdx.x * 8 + wid;
    if (dst >= n) return;

    const int ch0 = lane * 4;

    unsigned long long weq[4][4];
    #pragma unroll
    for (int p = 0; p < 4; p++)
        #pragma unroll
        for (int v = 0; v < 4; v++)
            weq[p][v] = pk2(__ldg(We + (2 * p) * D + ch0 + v),
                            __ldg(We + (2 * p + 1) * D + ch0 + v));

    float attv[4], xrv[4], num[4];
    float den = 0.f;
    {
        float4 a = __ldg((const float4*)(att + ch0));
        attv[0] = a.x; attv[1] = a.y; attv[2] = a.z; attv[3] = a.w;
        float4 r = *(const float4*)(xr + (size_t)dst * D + ch0);
        xrv[0] = r.x; xrv[1] = r.y; xrv[2] = r.z; xrv[3] = r.w;
    }
    #pragma unroll
    for (int v = 0; v < 4; v++) num[v] = 0.f;

    auto ldX = [&](float* d, const float* p) {
        float4 t = *(const float4*)p;
        d[0] = t.x; d[1] = t.y; d[2] = t.z; d[3] = t.w;
    };
    auto ldE = [&](unsigned long long* d, const float* p) {
        ulonglong2 a = *(const ulonglong2*)p;
        ulonglong2 b = *(const ulonglong2*)(p + 4);
        d[0] = a.x; d[1] = a.y; d[2] = b.x; d[3] = b.y;
    };
    auto body = [&](const float* xv, const unsigned long long* ep) {
        float pp = 0.f;
        #pragma unroll
        for (int v = 0; v < 4; v++) {
            unsigned long long acc = fmul2_(ep[3], weq[3][v]);
            acc = ffma2_(ep[2], weq[2][v], acc);
            acc = ffma2_(ep[1], weq[1][v], acc);
            acc = ffma2_(ep[0], weq[0][v], acc);
            float lo, hi;
            upk2(acc, lo, hi);
            float t = lo + hi + xv[v] + xrv[v];
            float s = fmaxf(t, 0.f) + 0.2f * fminf(t, 0.f);
            pp = fmaf(s, attv[v], pp);
        }
        pp += __shfl_xor_sync(0xffffffffu, pp, 4);
        pp += __shfl_xor_sync(0xffffffffu, pp, 2);
        pp += __shfl_xor_sync(0xffffffffu, pp, 1);
        float w = __expf(pp);
        #pragma unroll
        for (int v = 0; v < 4; v++) num[v] = fmaf(w, xv[v], num[v]);
        den += w;
    };

    int rs = rowptr[dst], re = rowptr[dst + 1];

    // depth-3 rotating pipeline, compile-time slots
    float px0[4], px1[4], px2[4];
    unsigned long long pe0[4], pe1[4], pe2[4];
#define PREF2(X, EA, IDX) do { int kk = (IDX); if (kk < re) { \
        int s_ = colsrc[kk]; \
        ldE(EA, eaP + (size_t)kk * 8); \
        ldX(X, xl + (size_t)s_ * D + ch0); } } while (0)
    PREF2(px0, pe0, rs);
    PREF2(px1, pe1, rs + 1);
    PREF2(px2, pe2, rs + 2);
    {   // self loop (its loads overlap the prefetches above)
        float sx[4];
        unsigned long long se[4];
        ldX(sx, xl + (size_t)dst * D + ch0);
        ldE(se, loopattr + (size_t)dst * 8);
        body(sx, se);
    }
    int k = rs;
    while (k < re) {
        {
            float cx[4];
            unsigned long long ce[4];
            #pragma unroll
            for (int v = 0; v < 4; v++) cx[v] = px0[v];
            #pragma unroll
            for (int q = 0; q < 4; q++) ce[q] = pe0[q];
            PREF2(px0, pe0, k + 3);
            body(cx, ce);
        }
        if (++k >= re) break;
        {
            float cx[4];
            unsigned long long ce[4];
            #pragma unroll
            for (int v = 0; v < 4; v++) cx[v] = px1[v];
            #pragma unroll
            for (int q = 0; q < 4; q++) ce[q] = pe1[q];
            PREF2(px1, pe1, k + 3);
            body(cx, ce);
        }
        if (++k >= re) break;
        {
            float cx[4];
            unsigned long long ce[4];
            #pragma unroll
            for (int v = 0; v < 4; v++) cx[v] = px2[v];
            #pragma unroll
            for (int q = 0; q < 4; q++) ce[q] = pe2[q];
            PREF2(px2, pe2, k + 3);
            body(cx, ce);
        }
        ++k;
    }
#undef PREF2

    float res[4];
    #pragma unroll
    for (int v = 0; v < 4; v++) {
        float val = num[v] / den;
        val += pre[(size_t)dst * D + ch0 + v];
        res[v] = fmaxf(val, 0.f);
    }
    *(float4*)&out[(size_t)dst * D + ch0] = make_float4(res[0], res[1], res[2], res[3]);
}

// ---------------- host launcher ----------------
extern "C" void kernel_launch(void* const* d_in, const int* in_sizes, int n_in,
                              void* d_out, int out_size) {
    const float* x     = (const float*)d_in[0];
    const int*   eidx  = (const int*)d_in[1];
    const float* eattr = (const float*)d_in[2];
    const float* Wl1 = (const float*)d_in[3];
    const float* bl1 = (const float*)d_in[4];
    const float* Wr1 = (const float*)d_in[5];
    const float* br1 = (const float*)d_in[6];
    const float* We1 = (const float*)d_in[7];
    const float* att1 = (const float*)d_in[8];
    const float* b1 = (const float*)d_in[9];
    const float* Wl2 = (const float*)d_in[10];
    const float* bl2 = (const float*)d_in[11];
    const float* Wr2 = (const float*)d_in[12];
    const float* br2 = (const float*)d_in[13];
    const float* We2 = (const float*)d_in[14];
    const float* att2 = (const float*)d_in[15];
    const float* b2 = (const float*)d_in[16];
    const float* Rw2 = (const float*)d_in[17];
    const float* Wl3 = (const float*)d_in[18];
    const float* bl3 = (const float*)d_in[19];
    const float* Wr3 = (const float*)d_in[20];
    const float* br3 = (const float*)d_in[21];
    const float* We3 = (const float*)d_in[22];
    const float* att3 = (const float*)d_in[23];
    const float* b3 = (const float*)d_in[24];

    int Nn = in_sizes[0] / 16;   // 50000
    int Ee = in_sizes[1] / 2;    // 800000
    const int* srcp = eidx;
    const int* dstp = eidx + Ee;

    float *xl, *xr, *res, *h1, *h2, *loopw, *eaP;
    int *deg, *rowptr, *wptr, *bsum, *colsrc;
    cudaGetSymbolAddress((void**)&xl, g_xl);
    cudaGetSymbolAddress((void**)&xr, g_xr);
    cudaGetSymbolAddress((void**)&res, g_res);
    cudaGetSymbolAddress((void**)&h1, g_h1);
    cudaGetSymbolAddress((void**)&h2, g_h2);
    cudaGetSymbolAddress((void**)&loopw, g_loop);
    cudaGetSymbolAddress((void**)&eaP, g_eaP);
    cudaGetSymbolAddress((void**)&deg, g_deg);
    cudaGetSymbolAddress((void**)&rowptr, g_rowptr);
    cudaGetSymbolAddress((void**)&wptr, g_wptr);
    cudaGetSymbolAddress((void**)&bsum, g_bsum);
    cudaGetSymbolAddress((void**)&colsrc, g_colsrc);

    int G = (Nn + 1023) / 1024;  // 49

    // ---- CSR + permuted eattr + self-loop attr ----
    // deg is zero at program start and re-zeroed by scanfinal each replay.
    hist_kernel<<<(Ee + 255) / 256, 256>>>(dstp, deg, Ee);
    blocksum_kernel<<<G, 1024>>>(deg, bsum, Nn);
    scanpart_kernel<<<1, 1024>>>(bsum, G);
    scanfinal_kernel<<<G, 1024>>>(deg, bsum, rowptr, wptr, Nn, Ee);
    scatter_kernel<<<(Ee + 255) / 256, 256>>>(srcp, dstp, eattr, wptr, colsrc, eaP, Ee);
    loopattr_kernel<<<(Nn * 8 + 255) / 256, 256>>>(rowptr, eaP, loopw, Nn);

    // ---- layer 1: in=16 -> D=32 (H=4), relu ----
    gemm_multi<16, 32, 2, 32, 16><<<(Nn + 31) / 32, 128>>>(
        x, Wl1, bl1, xl, Wr1, br1, xr, nullptr, nullptr, nullptr, Nn);
    agg_kernel<8, true><<<(Nn + 7) / 8, 256>>>(
        xl, xr, eaP, We1, att1, b1, rowptr, colsrc, loopw, h1, Nn);

    // ---- layer 2: in=32 -> D=128 (H=4), residual h1@Rw2 + b2, relu (3 GEMMs fused) ----
    gemm_multi<32, 128, 3, 16, 32><<<(Nn + 15) / 16, 384>>>(
        h1, Wl2, bl2, xl, Wr2, br2, xr, Rw2, b2, res, Nn);
    agg2_kernel<<<(Nn + 7) / 8, 256>>>(
        xl, xr, eaP, We2, att2, res, rowptr, colsrc, loopw, h2, Nn);

    // ---- layer 3: in=128 -> D=32 (H=1), no relu ----
    gemm_multi<128, 32, 2, 32, 32><<<(Nn + 31) / 32, 128>>>(
        h2, Wl3, bl3, xl, Wr3, br3, xr, nullptr, nullptr, nullptr, Nn);
    agg_kernel<32, false><<<(Nn + 7) / 8, 256>>>(
        xl, xr, eaP, We3, att3, b3, rowptr, colsrc, loopw, (float*)d_out, Nn);
}

// round 16
// speedup vs baseline: 1.1391x; 1.0789x over previous
#include <cuda_runtime.h>
#include <math.h>

#define NNODES 50000
#define NEDGES 800000

// ---------------- f32x2 packed-math helpers (sm_103a FFMA2) ----------------
__device__ __forceinline__ unsigned long long pk2(float lo, float hi) {
    unsigned long long r;
    asm("mov.b64 %0, {%1, %2};" : "=l"(r) : "f"(lo), "f"(hi));
    return r;
}
__device__ __forceinline__ unsigned long long spl2(float x) {
    unsigned long long r;
    asm("mov.b64 %0, {%1, %1};" : "=l"(r) : "f"(x));
    return r;
}
__device__ __forceinline__ void upk2(unsigned long long v, float& lo, float& hi) {
    asm("mov.b64 {%0, %1}, %2;" : "=f"(lo), "=f"(hi) : "l"(v));
}
__device__ __forceinline__ unsigned long long ffma2_(unsigned long long a,
                                                    unsigned long long b,
                                                    unsigned long long c) {
    unsigned long long d;
    asm("fma.rn.f32x2 %0, %1, %2, %3;" : "=l"(d) : "l"(a), "l"(b), "l"(c));
    return d;
}
__device__ __forceinline__ unsigned long long fmul2_(unsigned long long a,
                                                     unsigned long long b) {
    unsigned long long d;
    asm("mul.rn.f32x2 %0, %1, %2;" : "=l"(d) : "l"(a), "l"(b));
    return d;
}

// ---------------- scratch (static __device__ — no allocations) ----------------
__device__ __align__(16) float g_xl[NNODES * 128];
__device__ __align__(16) float g_xr[NNODES * 128];
__device__ __align__(16) float g_res[NNODES * 128];
__device__ __align__(16) float g_h1[NNODES * 32];
__device__ __align__(16) float g_h2[NNODES * 128];
__device__ __align__(16) float g_loop[NNODES * 8];
__device__ __align__(16) float g_eaP[NEDGES * 8];    // edge_attr permuted to CSR order
__device__ int g_deg[NNODES];                        // zero-invariant across replays
__device__ int g_rowptr[NNODES + 1];
__device__ int g_wptr[NNODES];
__device__ int g_bsum[1024];
__device__ int g_colsrc[NEDGES];

// ---------------- CSR build ----------------
__global__ void hist_kernel(const int* __restrict__ dst, int* __restrict__ deg, int e) {
    int i = blockIdx.x * blockDim.x + threadIdx.x;
    if (i < e) atomicAdd(&deg[dst[i]], 1);
}

__global__ void blocksum_kernel(const int* __restrict__ deg, int* __restrict__ bsum, int n) {
    __shared__ int sh[32];
    int tid = threadIdx.x, lane = tid & 31, wid = tid >> 5;
    int i = blockIdx.x * 1024 + tid;
    int v = (i < n) ? deg[i] : 0;
    #pragma unroll
    for (int off = 16; off > 0; off >>= 1) v += __shfl_xor_sync(0xffffffffu, v, off);
    if (lane == 0) sh[wid] = v;
    __syncthreads();
    if (wid == 0) {
        int x = sh[lane];
        #pragma unroll
        for (int off = 16; off > 0; off >>= 1) x += __shfl_xor_sync(0xffffffffu, x, off);
        if (lane == 0) bsum[blockIdx.x] = x;
    }
}

__global__ void scanpart_kernel(int* __restrict__ b, int g) {
    __shared__ int ws[32];
    int tid = threadIdx.x, lane = tid & 31, wid = tid >> 5;
    int v = (tid < g) ? b[tid] : 0;
    int x = v;
    #pragma unroll
    for (int off = 1; off < 32; off <<= 1) {
        int t = __shfl_up_sync(0xffffffffu, x, off);
        if (lane >= off) x += t;
    }
    if (lane == 31) ws[wid] = x;
    __syncthreads();
    if (wid == 0) {
        int y = ws[lane];
        #pragma unroll
        for (int off = 1; off < 32; off <<= 1) {
            int t = __shfl_up_sync(0xffffffffu, y, off);
            if (lane >= off) y += t;
        }
        ws[lane] = y;
    }
    __syncthreads();
    int excl = x - v + (wid > 0 ? ws[wid - 1] : 0);
    if (tid < g) b[tid] = excl;
}

// final scan: writes rowptr & wptr, AND re-zeroes deg (restores invariant)
__global__ void scanfinal_kernel(int* __restrict__ deg, const int* __restrict__ bsum,
                                 int* __restrict__ rowptr, int* __restrict__ wptr,
                                 int n, int e) {
    __shared__ int ws[32];
    int tid = threadIdx.x, lane = tid & 31, wid = tid >> 5;
    int i = blockIdx.x * 1024 + tid;
    int v = (i < n) ? deg[i] : 0;
    if (i < n) deg[i] = 0;
    int x = v;
    #pragma unroll
    for (int off = 1; off < 32; off <<= 1) {
        int t = __shfl_up_sync(0xffffffffu, x, off);
        if (lane >= off) x += t;
    }
    if (lane == 31) ws[wid] = x;
    __syncthreads();
    if (wid == 0) {
        int y = ws[lane];
        #pragma unroll
        for (int off = 1; off < 32; off <<= 1) {
            int t = __shfl_up_sync(0xffffffffu, y, off);
            if (lane >= off) y += t;
        }
        ws[lane] = y;
    }
    __syncthreads();
    int excl = x - v + (wid > 0 ? ws[wid - 1] : 0) + bsum[blockIdx.x];
    if (i < n) { rowptr[i] = excl; wptr[i] = excl; }
    if (blockIdx.x == 0 && tid == 0) rowptr[n] = e;
}

// scatter src ids AND permute edge_attr into CSR order (eaP)
__global__ void scatter_kernel(const int* __restrict__ src, const int* __restrict__ dst,
                               const float* __restrict__ eattr, int* __restrict__ wptr,
                               int* __restrict__ colsrc, float* __restrict__ eaP, int e) {
    int i = blockIdx.x * blockDim.x + threadIdx.x;
    if (i >= e) return;
    int d = dst[i];
    int p = atomicAdd(&wptr[d], 1);
    colsrc[p] = src[i];
    float4 a = *(const float4*)(eattr + (size_t)i * 8);
    float4 b = *(const float4*)(eattr + (size_t)i * 8 + 4);
    *(float4*)(eaP + (size_t)p * 8) = a;
    *(float4*)(eaP + (size_t)p * 8 + 4) = b;
}

// loop-attr mean from CSR (coalesced sequential reads of eaP), divide folded in
__global__ void loopattr_kernel(const int* __restrict__ rowptr, const float* __restrict__ eaP,
                                float* __restrict__ loopv, int n) {
    int tid = blockIdx.x * blockDim.x + threadIdx.x;
    int g = tid >> 3, c = tid & 7;
    if (g >= n) return;
    int rs = rowptr[g], re = rowptr[g + 1];
    float s = 0.f;
    for (int k = rs; k < re; k++) s += eaP[(size_t)k * 8 + c];
    int d = re - rs;
    loopv[g * 8 + c] = s / (float)(d > 0 ? d : 1);
}

// ---------------- dense GEMM: up to NW weight sets sharing A (f32x2 inner) ----------------
template <int K, int DOUT, int NW, int ROWS, int KC>
__global__ void gemm_multi(const float* __restrict__ A,
                           const float* __restrict__ W0, const float* __restrict__ b0, float* __restrict__ O0,
                           const float* __restrict__ W1, const float* __restrict__ b1, float* __restrict__ O1,
                           const float* __restrict__ W2, const float* __restrict__ b2, float* __restrict__ O2,
                           int n) {
    constexpr int COLS = DOUT * NW;
    constexpr int TX = COLS / 4;
    constexpr int TY = ROWS / 4;
    constexpr int NT = TX * TY;
    constexpr bool STAGE = (K * COLS * 4 <= 40960);
    constexpr int SWSZ = STAGE ? K * COLS : 4;
    __shared__ __align__(16) float sW[SWSZ];
    __shared__ float sA[KC][ROWS + 1];
    int tid = threadIdx.x;
    if (STAGE) {
        for (int idx = tid; idx < K * DOUT; idx += NT) {
            int k = idx / DOUT, c = idx % DOUT;
            sW[k * COLS + c] = W0[idx];
            if (NW > 1) sW[k * COLS + DOUT + c] = W1[idx];
            if (NW > 2) sW[k * COLS + 2 * DOUT + c] = W2[idx];
        }
    }
    int tx = tid % TX, ty = tid / TX;
    int cg = tx * 4;
    int which = cg / DOUT, col = cg % DOUT;
    const float* bb = (which == 0) ? b0 : (which == 1) ? b1 : b2;
    const float* Wp = (which == 0) ? W0 : (which == 1) ? W1 : W2;
    int row0 = blockIdx.x * ROWS;

    unsigned long long a01[4], a23[4];
    {
        unsigned long long i01 = pk2(bb[col + 0], bb[col + 1]);
        unsigned long long i23 = pk2(bb[col + 2], bb[col + 3]);
        #pragma unroll
        for (int i = 0; i < 4; i++) { a01[i] = i01; a23[i] = i23; }
    }

    for (int kc0 = 0; kc0 < K; kc0 += KC) {
        __syncthreads();
        for (int idx = tid; idx < ROWS * KC; idx += NT) {
            int r = idx / KC, k = idx % KC;
            int gr = row0 + r;
            sA[k][r] = (gr < n) ? A[(size_t)gr * K + kc0 + k] : 0.f;
        }
        __syncthreads();
        #pragma unroll
        for (int k = 0; k < KC; k++) {
            unsigned long long rb01, rb23;
            if (STAGE) {
                ulonglong2 rbp = *(const ulonglong2*)&sW[(kc0 + k) * COLS + cg];
                rb01 = rbp.x; rb23 = rbp.y;
            } else {
                ulonglong2 rbp = *(const ulonglong2*)&Wp[(size_t)(kc0 + k) * DOUT + col];
                rb01 = rbp.x; rb23 = rbp.y;
            }
            #pragma unroll
            for (int i = 0; i < 4; i++) {
                unsigned long long ras = spl2(sA[k][ty * 4 + i]);
                a01[i] = ffma2_(ras, rb01, a01[i]);
                a23[i] = ffma2_(ras, rb23, a23[i]);
            }
        }
    }
    float* O = (which == 0) ? O0 : (which == 1) ? O1 : O2;
    #pragma unroll
    for (int i = 0; i < 4; i++) {
        int gr = row0 + ty * 4 + i;
        if (gr < n) {
            float v0, v1, v2, v3;
            upk2(a01[i], v0, v1);
            upk2(a23[i], v2, v3);
            *(float4*)&O[(size_t)gr * DOUT + col] = make_float4(v0, v1, v2, v3);
        }
    }
}

// ---------------- D=32 edge pass: 4 dsts per warp (8-lane groups) ----------------
// Group g = lane>>3 owns one dst; sub-lane sl = lane&7 owns channels sl*4..sl*4+3.
//   layer1 (H=4, C=8): head = 2 lanes -> HG=2 (1 shfl per iteration, 4 edges)
//   layer3 (H=1):      head = group  -> HG=8 (3 shfls per iteration, 4 edges)
// Bodies are always warp-converged (shfl-safe); per-group validity via w=0.
template <int HG, bool RELU>
__global__ __launch_bounds__(256) void aggq_kernel(
    const float* __restrict__ xl, const float* __restrict__ xr,
    const float* __restrict__ eaP, const float* __restrict__ We,
    const float* __restrict__ att, const float* __restrict__ bias,
    const int* __restrict__ rowptr, const int* __restrict__ colsrc,
    const float* __restrict__ loopattr, float* __restrict__ out, int n) {
    constexpr int D = 32;
    int tid = threadIdx.x, lane = tid & 31, wid = tid >> 5;
    int sl = lane & 7;
    int dst = blockIdx.x * 32 + wid * 4 + (lane >> 3);
    bool vd = dst < n;
    int ds = vd ? dst : 0;
    const int ch0 = sl * 4;

    float rWe[8][4];
    #pragma unroll
    for (int q = 0; q < 8; q++) {
        float4 w = __ldg((const float4*)(We + q * D + ch0));
        rWe[q][0] = w.x; rWe[q][1] = w.y; rWe[q][2] = w.z; rWe[q][3] = w.w;
    }

    float attv[4], xrv[4], num[4];
    float den = 0.f;
    {
        float4 a = __ldg((const float4*)(att + ch0));
        attv[0] = a.x; attv[1] = a.y; attv[2] = a.z; attv[3] = a.w;
        float4 r = *(const float4*)(xr + (size_t)ds * D + ch0);
        xrv[0] = r.x; xrv[1] = r.y; xrv[2] = r.z; xrv[3] = r.w;
    }
    #pragma unroll
    for (int v = 0; v < 4; v++) num[v] = 0.f;

    auto ldX = [&](float* d, const float* p) {
        float4 t = *(const float4*)p;
        d[0] = t.x; d[1] = t.y; d[2] = t.z; d[3] = t.w;
    };
    auto ldE = [&](float* d, const float* p) {
        float4 a = *(const float4*)p;
        float4 b = *(const float4*)(p + 4);
        d[0] = a.x; d[1] = a.y; d[2] = a.z; d[3] = a.w;
        d[4] = b.x; d[5] = b.y; d[6] = b.z; d[7] = b.w;
    };
    auto body = [&](const float* xv, const float* ev, bool valid) {
        float m[4];
        #pragma unroll
        for (int v = 0; v < 4; v++) m[v] = 0.f;
        #pragma unroll
        for (int q = 0; q < 8; q++)
            #pragma unroll
            for (int v = 0; v < 4; v++)
                m[v] = fmaf(ev[q], rWe[q][v], m[v]);
        float p = 0.f;
        #pragma unroll
        for (int v = 0; v < 4; v++) {
            float t = m[v] + xv[v] + xrv[v];
            float s = fmaxf(t, 0.f) + 0.2f * fminf(t, 0.f);
            p = fmaf(s, attv[v], p);
        }
        #pragma unroll
        for (int off = HG / 2; off > 0; off >>= 1)
            p += __shfl_xor_sync(0xffffffffu, p, off);
        float w = __expf(p);
        if (!valid) w = 0.f;
        #pragma unroll
        for (int v = 0; v < 4; v++) num[v] = fmaf(w, xv[v], num[v]);
        den += w;
    };

    int rs = rowptr[ds];
    int re = vd ? rowptr[ds + 1] : rs;

    // depth-2 pipeline per group; zero-init so idle groups stay finite
    float xb0[4], xb1[4], eb0[8], eb1[8];
    #pragma unroll
    for (int v = 0; v < 4; v++) { xb0[v] = 0.f; xb1[v] = 0.f; }
    #pragma unroll
    for (int q = 0; q < 8; q++) { eb0[q] = 0.f; eb1[q] = 0.f; }
    if (rs < re) {
        int s = colsrc[rs];
        ldE(eb0, eaP + (size_t)rs * 8);
        ldX(xb0, xl + (size_t)s * D + ch0);
    }
    if (rs + 1 < re) {
        int s = colsrc[rs + 1];
        ldE(eb1, eaP + (size_t)(rs + 1) * 8);
        ldX(xb1, xl + (size_t)s * D + ch0);
    }
    {   // self loop (loads overlap prefetches above); valid = vd
        float sx[4], se[8];
        ldX(sx, xl + (size_t)ds * D + ch0);
        ldE(se, loopattr + (size_t)ds * 8);
        body(sx, se, vd);
    }
    int k = rs;
    while (__any_sync(0xffffffffu, k < re)) {
        {
            bool v0 = k < re;
            float cx[4], ce[8];
            #pragma unroll
            for (int v = 0; v < 4; v++) cx[v] = xb0[v];
            #pragma unroll
            for (int q = 0; q < 8; q++) ce[q] = eb0[q];
            if (k + 2 < re) {
                int s = colsrc[k + 2];
                ldE(eb0, eaP + (size_t)(k + 2) * 8);
                ldX(xb0, xl + (size_t)s * D + ch0);
            }
            body(cx, ce, v0);
        }
        k++;
        if (!__any_sync(0xffffffffu, k < re)) break;
        {
            bool v1 = k < re;
            float cx[4], ce[8];
            #pragma unroll
            for (int v = 0; v < 4; v++) cx[v] = xb1[v];
            #pragma unroll
            for (int q = 0; q < 8; q++) ce[q] = eb1[q];
            if (k + 2 < re) {
                int s = colsrc[k + 2];
                ldE(eb1, eaP + (size_t)(k + 2) * 8);
                ldX(xb1, xl + (size_t)s * D + ch0);
            }
            body(cx, ce, v1);
        }
        k++;
    }

    if (vd) {
        float res[4];
        #pragma unroll
        for (int v = 0; v < 4; v++) {
            float val = num[v] / den;
            if (bias) val += bias[ch0 + v];
            if (RELU) val = fmaxf(val, 0.f);
            res[v] = val;
        }
        *(float4*)&out[(size_t)dst * D + ch0] = make_float4(res[0], res[1], res[2], res[3]);
    }
}

// ---------------- layer-2 edge pass: D=128, H=4, q-packed f32x2 body ----------------
// lane owns channels lane*4..lane*4+3 (all in head lane>>3 -> GROUP=8 reduce).
// Depth-3 rotating software pipeline.
__global__ __launch_bounds__(256) void agg2_kernel(
    const float* __restrict__ xl, const float* __restrict__ xr,
    const float* __restrict__ eaP, const float* __restrict__ We,
    const float* __restrict__ att, const float* __restrict__ pre,
    const int* __restrict__ rowptr, const int* __restrict__ colsrc,
    const float* __restrict__ loopattr, float* __restrict__ out, int n) {
    constexpr int D = 128;
    int tid = threadIdx.x, lane = tid & 31, wid = tid >> 5;
    int dst = blockIdx.x * 8 + wid;
    if (dst >= n) return;

    const int ch0 = lane * 4;

    unsigned long long weq[4][4];
    #pragma unroll
    for (int p = 0; p < 4; p++)
        #pragma unroll
        for (int v = 0; v < 4; v++)
            weq[p][v] = pk2(__ldg(We + (2 * p) * D + ch0 + v),
                            __ldg(We + (2 * p + 1) * D + ch0 + v));

    float attv[4], xrv[4], num[4];
    float den = 0.f;
    {
        float4 a = __ldg((const float4*)(att + ch0));
        attv[0] = a.x; attv[1] = a.y; attv[2] = a.z; attv[3] = a.w;
        float4 r = *(const float4*)(xr + (size_t)dst * D + ch0);
        xrv[0] = r.x; xrv[1] = r.y; xrv[2] = r.z; xrv[3] = r.w;
    }
    #pragma unroll
    for (int v = 0; v < 4; v++) num[v] = 0.f;

    auto ldX = [&](float* d, const float* p) {
        float4 t = *(const float4*)p;
        d[0] = t.x; d[1] = t.y; d[2] = t.z; d[3] = t.w;
    };
    auto ldE = [&](unsigned long long* d, const float* p) {
        ulonglong2 a = *(const ulonglong2*)p;
        ulonglong2 b = *(const ulonglong2*)(p + 4);
        d[0] = a.x; d[1] = a.y; d[2] = b.x; d[3] = b.y;
    };
    auto body = [&](const float* xv, const unsigned long long* ep) {
        float pp = 0.f;
        #pragma unroll
        for (int v = 0; v < 4; v++) {
            unsigned long long acc = fmul2_(ep[3], weq[3][v]);
            acc = ffma2_(ep[2], weq[2][v], acc);
            acc = ffma2_(ep[1], weq[1][v], acc);
            acc = ffma2_(ep[0], weq[0][v], acc);
            float lo, hi;
            upk2(acc, lo, hi);
            float t = lo + hi + xv[v] + xrv[v];
            float s = fmaxf(t, 0.f) + 0.2f * fminf(t, 0.f);
            pp = fmaf(s, attv[v], pp);
        }
        pp += __shfl_xor_sync(0xffffffffu, pp, 4);
        pp += __shfl_xor_sync(0xffffffffu, pp, 2);
        pp += __shfl_xor_sync(0xffffffffu, pp, 1);
        float w = __expf(pp);
        #pragma unroll
        for (int v = 0; v < 4; v++) num[v] = fmaf(w, xv[v], num[v]);
        den += w;
    };

    int rs = rowptr[dst], re = rowptr[dst + 1];

    float px0[4], px1[4], px2[4];
    unsigned long long pe0[4], pe1[4], pe2[4];
#define PREF2(X, EA, IDX) do { int kk = (IDX); if (kk < re) { \
        int s_ = colsrc[kk]; \
        ldE(EA, eaP + (size_t)kk * 8); \
        ldX(X, xl + (size_t)s_ * D + ch0); } } while (0)
    PREF2(px0, pe0, rs);
    PREF2(px1, pe1, rs + 1);
    PREF2(px2, pe2, rs + 2);
    {   // self loop (its loads overlap the prefetches above)
        float sx[4];
        unsigned long long se[4];
        ldX(sx, xl + (size_t)dst * D + ch0);
        ldE(se, loopattr + (size_t)dst * 8);
        body(sx, se);
    }
    int k = rs;
    while (k < re) {
        {
            float cx[4];
            unsigned long long ce[4];
            #pragma unroll
            for (int v = 0; v < 4; v++) cx[v] = px0[v];
            #pragma unroll
            for (int q = 0; q < 4; q++) ce[q] = pe0[q];
            PREF2(px0, pe0, k + 3);
            body(cx, ce);
        }
        if (++k >= re) break;
        {
            float cx[4];
            unsigned long long ce[4];
            #pragma unroll
            for (int v = 0; v < 4; v++) cx[v] = px1[v];
            #pragma unroll
            for (int q = 0; q < 4; q++) ce[q] = pe1[q];
            PREF2(px1, pe1, k + 3);
            body(cx, ce);
        }
        if (++k >= re) break;
        {
            float cx[4];
            unsigned long long ce[4];
            #pragma unroll
            for (int v = 0; v < 4; v++) cx[v] = px2[v];
            #pragma unroll
            for (int q = 0; q < 4; q++) ce[q] = pe2[q];
            PREF2(px2, pe2, k + 3);
            body(cx, ce);
        }
        ++k;
    }
#undef PREF2

    float res[4];
    #pragma unroll
    for (int v = 0; v < 4; v++) {
        float val = num[v] / den;
        val += pre[(size_t)dst * D + ch0 + v];
        res[v] = fmaxf(val, 0.f);
    }
    *(float4*)&out[(size_t)dst * D + ch0] = make_float4(res[0], res[1], res[2], res[3]);
}

// ---------------- host launcher ----------------
extern "C" void kernel_launch(void* const* d_in, const int* in_sizes, int n_in,
                              void* d_out, int out_size) {
    const float* x     = (const float*)d_in[0];
    const int*   eidx  = (const int*)d_in[1];
    const float* eattr = (const float*)d_in[2];
    const float* Wl1 = (const float*)d_in[3];
    const float* bl1 = (const float*)d_in[4];
    const float* Wr1 = (const float*)d_in[5];
    const float* br1 = (const float*)d_in[6];
    const float* We1 = (const float*)d_in[7];
    const float* att1 = (const float*)d_in[8];
    const float* b1 = (const float*)d_in[9];
    const float* Wl2 = (const float*)d_in[10];
    const float* bl2 = (const float*)d_in[11];
    const float* Wr2 = (const float*)d_in[12];
    const float* br2 = (const float*)d_in[13];
    const float* We2 = (const float*)d_in[14];
    const float* att2 = (const float*)d_in[15];
    const float* b2 = (const float*)d_in[16];
    const float* Rw2 = (const float*)d_in[17];
    const float* Wl3 = (const float*)d_in[18];
    const float* bl3 = (const float*)d_in[19];
    const float* Wr3 = (const float*)d_in[20];
    const float* br3 = (const float*)d_in[21];
    const float* We3 = (const float*)d_in[22];
    const float* att3 = (const float*)d_in[23];
    const float* b3 = (const float*)d_in[24];

    int Nn = in_sizes[0] / 16;   // 50000
    int Ee = in_sizes[1] / 2;    // 800000
    const int* srcp = eidx;
    const int* dstp = eidx + Ee;

    float *xl, *xr, *res, *h1, *h2, *loopw, *eaP;
    int *deg, *rowptr, *wptr, *bsum, *colsrc;
    cudaGetSymbolAddress((void**)&xl, g_xl);
    cudaGetSymbolAddress((void**)&xr, g_xr);
    cudaGetSymbolAddress((void**)&res, g_res);
    cudaGetSymbolAddress((void**)&h1, g_h1);
    cudaGetSymbolAddress((void**)&h2, g_h2);
    cudaGetSymbolAddress((void**)&loopw, g_loop);
    cudaGetSymbolAddress((void**)&eaP, g_eaP);
    cudaGetSymbolAddress((void**)&deg, g_deg);
    cudaGetSymbolAddress((void**)&rowptr, g_rowptr);
    cudaGetSymbolAddress((void**)&wptr, g_wptr);
    cudaGetSymbolAddress((void**)&bsum, g_bsum);
    cudaGetSymbolAddress((void**)&colsrc, g_colsrc);

    int G = (Nn + 1023) / 1024;  // 49

    // ---- CSR + permuted eattr + self-loop attr ----
    hist_kernel<<<(Ee + 255) / 256, 256>>>(dstp, deg, Ee);
    blocksum_kernel<<<G, 1024>>>(deg, bsum, Nn);
    scanpart_kernel<<<1, 1024>>>(bsum, G);
    scanfinal_kernel<<<G, 1024>>>(deg, bsum, rowptr, wptr, Nn, Ee);
    scatter_kernel<<<(Ee + 255) / 256, 256>>>(srcp, dstp, eattr, wptr, colsrc, eaP, Ee);
    loopattr_kernel<<<(Nn * 8 + 255) / 256, 256>>>(rowptr, eaP, loopw, Nn);

    // ---- layer 1: in=16 -> D=32 (H=4), relu ----
    gemm_multi<16, 32, 2, 32, 16><<<(Nn + 31) / 32, 128>>>(
        x, Wl1, bl1, xl, Wr1, br1, xr, nullptr, nullptr, nullptr, Nn);
    aggq_kernel<2, true><<<(Nn + 31) / 32, 256>>>(
        xl, xr, eaP, We1, att1, b1, rowptr, colsrc, loopw, h1, Nn);

    // ---- layer 2: in=32 -> D=128 (H=4), residual h1@Rw2 + b2, relu (3 GEMMs fused) ----
    gemm_multi<32, 128, 3, 16, 32><<<(Nn + 15) / 16, 384>>>(
        h1, Wl2, bl2, xl, Wr2, br2, xr, Rw2, b2, res, Nn);
    agg2_kernel<<<(Nn + 7) / 8, 256>>>(
        xl, xr, eaP, We2, att2, res, rowptr, colsrc, loopw, h2, Nn);

    // ---- layer 3: in=128 -> D=32 (H=1), no relu ----
    gemm_multi<128, 32, 2, 32, 32><<<(Nn + 31) / 32, 128>>>(
        h2, Wl3, bl3, xl, Wr3, br3, xr, nullptr, nullptr, nullptr, Nn);
    aggq_kernel<8, false><<<(Nn + 31) / 32, 256>>>(
        xl, xr, eaP, We3, att3, b3, rowptr, colsrc, loopw, (float*)d_out, Nn);
}